// round 6
// baseline (speedup 1.0000x reference)
#include <cuda_runtime.h>

#define NT   256
#define TT   512
#define ROWP 68      // padded row stride (floats) for 16x64 tiles

// packed fp32x2 FMA (sm_103a FFMA2) and splat helpers
#define FMA2(d, a, b, c) \
    asm("fma.rn.f32x2 %0, %1, %2, %3;" : "=l"(d) : "l"(a), "l"(b), "l"(c))
#define SPLAT(d, s) \
    asm("mov.b64 %0, {%1, %1};" : "=l"(d) : "f"(s))

union F2U { float2 f; unsigned long long u; };

__global__ __launch_bounds__(NT, 1)
void ttt_kernel(const float* __restrict__ XQ, const float* __restrict__ XK,
                const float* __restrict__ XV, const float* __restrict__ W1,
                const float* __restrict__ b1, const float* __restrict__ gam,
                const float* __restrict__ bet, float* __restrict__ out)
{
    __shared__ float W[4096];            // W[d*64+f], carried
    __shared__ float xq_s[2][16*ROWP];   // double-buffered tiles
    __shared__ float xk_s[2][16*ROWP];
    __shared__ float gz_s[16*ROWP];
    __shared__ float bb[64];             // carried bias
    __shared__ float eta_s[2][16];

    const int tid = threadIdx.x;
    const int bh  = blockIdx.x;
    const int h   = bh & 15;
    const int k   = tid >> 4;            // token row 0..15
    const int q   = tid & 15;
    const int f0  = q << 2;              // 4 features per thread

    const size_t base = (size_t)bh * (TT * 1024);
    const float* xqg = XQ + base;
    const float* xkg = XK + base;
    const float* xvg = XV + base;
    float*       og  = out + base;

    // ---- init carried state ----
    {
        const float* Wg = W1 + (size_t)h * 4096;
        #pragma unroll
        for (int i = 0; i < 4; i++)
            *(float4*)&W[i*1024 + tid*4] = *(const float4*)&Wg[i*1024 + tid*4];
        if (tid < 16)
            *(float4*)&bb[tid*4] = *(const float4*)&b1[h*64 + tid*4];
    }
    const float4 g4  = *(const float4*)&gam[h*64 + f0];
    const float4 be4 = *(const float4*)&bet[h*64 + f0];

    // ---- stage step 0 tiles + eta0 into buffer 0 ----
    float4 q4 = *(const float4*)&xqg[tid*4];
    float4 k4 = *(const float4*)&xkg[tid*4];
    float4 v4 = *(const float4*)&xvg[tid*4];
    *(float4*)&xq_s[0][k*ROWP + f0] = q4;
    *(float4*)&xk_s[0][k*ROWP + f0] = k4;
    {
        float ss = k4.x*k4.x + k4.y*k4.y + k4.z*k4.z + k4.w*k4.w;
        #pragma unroll
        for (int m = 8; m >= 1; m >>= 1) ss += __shfl_xor_sync(~0u, ss, m, 16);
        if (q == 0) eta_s[0][k] = 0.01f / (1.0f + fmaxf(sqrtf(ss), 1e-6f));
    }
    __syncthreads();

    int p = 0;
    for (int t = 0; t < TT; t++) {
        // ---- prefetch next step's tiles early (hide DRAM) ----
        float4 nq4 = make_float4(0.f,0.f,0.f,0.f), nk4 = nq4, nv4 = nq4;
        if (t + 1 < TT) {
            const size_t off = (size_t)(t+1)*1024 + tid*4;
            nq4 = *(const float4*)&xqg[off];
            nk4 = *(const float4*)&xkg[off];
            nv4 = *(const float4*)&xvg[off];
        }

        // em = mean(eta), el = eta[15] (precomputed last step)
        float em, el;
        {
            const float4 e0 = *(const float4*)&eta_s[p][0];
            const float4 e1 = *(const float4*)&eta_s[p][4];
            const float4 e2 = *(const float4*)&eta_s[p][8];
            const float4 e3 = *(const float4*)&eta_s[p][12];
            em = ((e0.x+e0.y+e0.z+e0.w) + (e1.x+e1.y+e1.z+e1.w)
                + (e2.x+e2.y+e2.z+e2.w) + (e3.x+e3.y+e3.z+e3.w)) * (1.0f/16.0f);
            el = e3.w;
        }

        // ---- fused: z=xk@W+b, zd=xq@W+b, a=xq[k].xk[q]+1 (FFMA2 path) ----
        const float* xqp = &xq_s[p][0];
        const float* xkp = &xk_s[p][0];
        F2U z01, z23, zd01, zd23;
        {
            const ulonglong2 b2 = *(const ulonglong2*)&bb[f0];
            z01.u = b2.x; z23.u = b2.y; zd01.u = b2.x; zd23.u = b2.y;
        }
        float a = 1.0f;
        #pragma unroll 4
        for (int j = 0; j < 16; j++) {
            const int d0 = j << 2;
            const float4 xk4 = *(const float4*)&xkp[k*ROWP + d0];
            const float4 xq4 = *(const float4*)&xqp[k*ROWP + d0];
            const float4 xkA = *(const float4*)&xkp[q*ROWP + d0];
            a = fmaf(xq4.x, xkA.x, a);
            a = fmaf(xq4.y, xkA.y, a);
            a = fmaf(xq4.z, xkA.z, a);
            a = fmaf(xq4.w, xkA.w, a);
            {
                const ulonglong2 w = *(const ulonglong2*)&W[(d0+0)*64 + f0];
                unsigned long long sk, sq;
                SPLAT(sk, xk4.x); SPLAT(sq, xq4.x);
                FMA2(z01.u,  sk, w.x, z01.u);  FMA2(z23.u,  sk, w.y, z23.u);
                FMA2(zd01.u, sq, w.x, zd01.u); FMA2(zd23.u, sq, w.y, zd23.u);
            }
            {
                const ulonglong2 w = *(const ulonglong2*)&W[(d0+1)*64 + f0];
                unsigned long long sk, sq;
                SPLAT(sk, xk4.y); SPLAT(sq, xq4.y);
                FMA2(z01.u,  sk, w.x, z01.u);  FMA2(z23.u,  sk, w.y, z23.u);
                FMA2(zd01.u, sq, w.x, zd01.u); FMA2(zd23.u, sq, w.y, zd23.u);
            }
            {
                const ulonglong2 w = *(const ulonglong2*)&W[(d0+2)*64 + f0];
                unsigned long long sk, sq;
                SPLAT(sk, xk4.z); SPLAT(sq, xq4.z);
                FMA2(z01.u,  sk, w.x, z01.u);  FMA2(z23.u,  sk, w.y, z23.u);
                FMA2(zd01.u, sq, w.x, zd01.u); FMA2(zd23.u, sq, w.y, zd23.u);
            }
            {
                const ulonglong2 w = *(const ulonglong2*)&W[(d0+3)*64 + f0];
                unsigned long long sk, sq;
                SPLAT(sk, xk4.w); SPLAT(sq, xq4.w);
                FMA2(z01.u,  sk, w.x, z01.u);  FMA2(z23.u,  sk, w.y, z23.u);
                FMA2(zd01.u, sq, w.x, zd01.u); FMA2(zd23.u, sq, w.y, zd23.u);
            }
        }

        // ---- LN(z) single-pass -> grad_Z1 ----
        const float zx = z01.f.x, zy = z01.f.y, zz = z23.f.x, zw = z23.f.y;
        float s1 = zx + zy + zz + zw;
        float s2 = zx*zx + zy*zy + zz*zz + zw*zw;
        #pragma unroll
        for (int m = 8; m >= 1; m >>= 1) {
            s1 += __shfl_xor_sync(~0u, s1, m, 16);
            s2 += __shfl_xor_sync(~0u, s2, m, 16);
        }
        const float mu  = s1 * 0.015625f;
        const float var = fmaf(-mu, mu, s2 * 0.015625f);
        const float r   = rsqrtf(var + 1e-6f);
        float4 gz;
        gz.x = 2.0f * (fmaf(g4.x, (zx-mu)*r, be4.x) - v4.x + k4.x);
        gz.y = 2.0f * (fmaf(g4.y, (zy-mu)*r, be4.y) - v4.y + k4.y);
        gz.z = 2.0f * (fmaf(g4.z, (zz-mu)*r, be4.z) - v4.z + k4.z);
        gz.w = 2.0f * (fmaf(g4.w, (zw-mu)*r, be4.w) - v4.w + k4.w);
        *(float4*)&gz_s[k*ROWP + f0] = gz;
        __syncthreads();                                   // S2

        // ---- carry update: rank-1, in place (FFMA2) ----
        {
            const ulonglong2 gl = *(const ulonglong2*)&gz_s[15*ROWP + f0];
            #pragma unroll
            for (int j = 0; j < 4; j++) {
                const int d = k + 16*j;
                const float cf = -el * xkp[15*ROWP + d];
                unsigned long long scf; SPLAT(scf, cf);
                ulonglong2 w4 = *(ulonglong2*)&W[d*64 + f0];
                FMA2(w4.x, scf, gl.x, w4.x);
                FMA2(w4.y, scf, gl.y, w4.y);
                *(ulonglong2*)&W[d*64 + f0] = w4;
            }
            if (tid < 16) {   // k==0, f0 == tid*4
                unsigned long long sel; SPLAT(sel, -el);
                ulonglong2 bv = *(ulonglong2*)&bb[f0];
                FMA2(bv.x, sel, gl.x, bv.x);
                FMA2(bv.y, sel, gl.y, bv.y);
                *(ulonglong2*)&bb[f0] = bv;
            }
        }

        // ---- correction: zd -= em * (A' @ gz), A' via half-warp shfl, FFMA2 ----
        F2U c01, c23; c01.u = 0ull; c23.u = 0ull;
        #pragma unroll
        for (int kp2 = 0; kp2 < 16; kp2++) {
            const float av = __shfl_sync(~0u, a, kp2, 16);
            unsigned long long sav; SPLAT(sav, av);
            const ulonglong2 gv = *(const ulonglong2*)&gz_s[kp2*ROWP + f0];
            FMA2(c01.u, sav, gv.x, c01.u);
            FMA2(c23.u, sav, gv.y, c23.u);
        }
        {
            unsigned long long sem; SPLAT(sem, -em);
            FMA2(zd01.u, sem, c01.u, zd01.u);
            FMA2(zd23.u, sem, c23.u, zd23.u);
        }

        // ---- LN(zd) single-pass, out = xq + ln ----
        const float dx = zd01.f.x, dy = zd01.f.y, dz = zd23.f.x, dw = zd23.f.y;
        float t1 = dx + dy + dz + dw;
        float t2 = dx*dx + dy*dy + dz*dz + dw*dw;
        #pragma unroll
        for (int m = 8; m >= 1; m >>= 1) {
            t1 += __shfl_xor_sync(~0u, t1, m, 16);
            t2 += __shfl_xor_sync(~0u, t2, m, 16);
        }
        const float mu2  = t1 * 0.015625f;
        const float var2 = fmaf(-mu2, mu2, t2 * 0.015625f);
        const float r2   = rsqrtf(var2 + 1e-6f);
        float4 o;
        o.x = q4.x + fmaf(g4.x, (dx-mu2)*r2, be4.x);
        o.y = q4.y + fmaf(g4.y, (dy-mu2)*r2, be4.y);
        o.z = q4.z + fmaf(g4.z, (dz-mu2)*r2, be4.z);
        o.w = q4.w + fmaf(g4.w, (dw-mu2)*r2, be4.w);
        *(float4*)&og[(size_t)t*1024 + tid*4] = o;

        // ---- stage NEXT step's tiles + eta into other buffer ----
        const int pn = p ^ 1;
        *(float4*)&xq_s[pn][k*ROWP + f0] = nq4;
        *(float4*)&xk_s[pn][k*ROWP + f0] = nk4;
        {
            float ss = nk4.x*nk4.x + nk4.y*nk4.y + nk4.z*nk4.z + nk4.w*nk4.w;
            #pragma unroll
            for (int m = 8; m >= 1; m >>= 1) ss += __shfl_xor_sync(~0u, ss, m, 16);
            if (q == 0) eta_s[pn][k] = 0.01f / (1.0f + fmaxf(sqrtf(ss), 1e-6f));
        }
        __syncthreads();                                   // S3

        q4 = nq4; k4 = nk4; v4 = nv4; p = pn;
    }
}

extern "C" void kernel_launch(void* const* d_in, const int* in_sizes, int n_in,
                              void* d_out, int out_size) {
    const float* XQ  = (const float*)d_in[0];
    const float* XK  = (const float*)d_in[1];
    const float* XV  = (const float*)d_in[2];
    const float* W1  = (const float*)d_in[3];
    const float* b1  = (const float*)d_in[4];
    const float* gam = (const float*)d_in[5];
    const float* bet = (const float*)d_in[6];
    float* out = (float*)d_out;

    const int nbh = in_sizes[0] / (TT * 16 * 64);   // B*H = 64
    ttt_kernel<<<nbh, NT>>>(XQ, XK, XV, W1, b1, gam, bet, out);
}